// round 4
// baseline (speedup 1.0000x reference)
#include <cuda_runtime.h>

// ---------------------------------------------------------------------------
// SpatialFrequencyLoss: sum_i w_i * mean( (LoG_i * (input - target))^2 )
// LoG kernel is rank-3 separable:  a = f (x) u  +  u (x) f  -  c * ones
// Row pass (along W): FH = (diff*f, diff*u) interleaved, A1 = diff*box
// Col pass (along H): d = f*Ah + u*Af - c*Box ; accumulate d^2
// All six sigmas fused per pass (blockIdx.z) so the chip stays full.
// Each sigma owns its OWN intermediate planes (row->col dependency!).
// Reflect padding (numpy 'reflect'), pad = K/2 < 512 always.
// ---------------------------------------------------------------------------

namespace {
constexpr int Hh = 512, Ww = 512, NCc = 4 * 3;
constexpr int NPIX = NCc * Hh * Ww;        // 3,145,728
constexpr int PWMAX = Ww + 2 * 77 + 2;     // 668, 16B-aligned rows
}

__device__ float  g_diff[NPIX];
__device__ float4 g_FH[6][NPIX / 2];   // per-sigma (Af,Ah) pairs, 2 px / float4
__device__ float4 g_A14[6][NPIX / 4];  // per-sigma A1 plane
__device__ double g_acc[6];

// ---------------- compile-time taps ----------------------------------------

__host__ __device__ constexpr double cexp(double x) {
    double r = x; int n = 0;
    while (r < -0.5) { r += 1.0; ++n; }
    double term = 1.0, sum = 1.0;
    for (int i = 1; i < 30; ++i) { term *= r / (double)i; sum += term; }
    for (int i = 0; i < n; ++i) sum /= 2.71828182845904523536028747135266;
    return sum;
}

template<int K> struct TapsT { float f[K]; float h[K]; float c; };

template<int K>
__host__ __device__ constexpr TapsT<K> make_taps(double sigma) {
    TapsT<K> T{};
    const double ss = sigma * sigma;
    const double norm = 1.0 / (2.0 * 3.14159265358979323846 * ss * ss);
    double Sf = 0.0, Sh = 0.0;
    for (int i = 0; i < K; ++i) {
        const double x = (double)(i - (K - 1) / 2);
        const double u = cexp(-(x * x) / (2.0 * ss));
        const double fv = (x * x - ss) * u * norm;
        T.f[i] = (float)fv;
        T.h[i] = (float)u;
        Sf += fv; Sh += u;
    }
    T.c = (float)(2.0 * Sf * Sh / ((double)K * (double)K));
    return T;
}

template<int SI> struct Cfg;
template<> struct Cfg<0> { static constexpr int K = 5;   static constexpr double S = 0.6;  static constexpr int CR = 16; };
template<> struct Cfg<1> { static constexpr int K = 11;  static constexpr double S = 1.2;  static constexpr int CR = 16; };
template<> struct Cfg<2> { static constexpr int K = 21;  static constexpr double S = 2.4;  static constexpr int CR = 16; };
template<> struct Cfg<3> { static constexpr int K = 39;  static constexpr double S = 4.8;  static constexpr int CR = 32; };
template<> struct Cfg<4> { static constexpr int K = 77;  static constexpr double S = 9.6;  static constexpr int CR = 32; };
template<> struct Cfg<5> { static constexpr int K = 155; static constexpr double S = 19.2; static constexpr int CR = 32; };

__device__ __forceinline__ int refl(int i, int n) {
    if (i < 0) i = -i;
    if (i >= n) i = 2 * n - 2 - i;
    return i;
}

// ---------------- diff ------------------------------------------------------

__global__ void diff_k(const float4* __restrict__ a, const float4* __restrict__ b) {
    if (blockIdx.x == 0 && threadIdx.x < 6) g_acc[threadIdx.x] = 0.0;
    int i = blockIdx.x * blockDim.x + threadIdx.x;
    if (i < NPIX / 4) {
        float4 x = a[i], y = b[i];
        float4 d;
        d.x = x.x - y.x; d.y = x.y - y.y; d.z = x.z - y.z; d.w = x.w - y.w;
        reinterpret_cast<float4*>(g_diff)[i] = d;
    }
}

// ---------------- row pass (all sigmas in one kernel) -----------------------
// 128 threads = 2 rows x 64 threads; 8 consecutive outputs/thread.
// Taps consumed 4 at a time from one LDS.128 via a linear shifting window.

template<int SI>
__device__ __forceinline__ void row_body(float* __restrict__ s, int tid, int row0) {
    constexpr int K = Cfg<SI>::K;
    constexpr TapsT<K> T = make_taps<K>(Cfg<SI>::S);
    constexpr int P = K / 2;
    constexpr int PW = Ww + 2 * P;

    // stage two padded rows
#pragma unroll
    for (int rr = 0; rr < 2; ++rr) {
        const float* __restrict__ src = g_diff + (row0 + rr) * Ww;
        for (int i = tid; i < PW; i += 128) s[rr * PWMAX + i] = src[refl(i - P, Ww)];
    }
    __syncthreads();

    const int sub = tid >> 6;
    const int x0  = (tid & 63) * 8;
    const float* __restrict__ sr = s + sub * PWMAX + x0;   // 16B aligned

    float w[12];
#pragma unroll
    for (int i = 0; i < 8; i += 4) {
        const float4 v = *reinterpret_cast<const float4*>(sr + i);
        w[i] = v.x; w[i + 1] = v.y; w[i + 2] = v.z; w[i + 3] = v.w;
    }

    float aF[8], aH[8];
#pragma unroll
    for (int o = 0; o < 8; ++o) { aF[o] = 0.f; aH[o] = 0.f; }
    float S = 0.f;

    constexpr int G = K / 4, REM = K % 4;
#pragma unroll
    for (int tg = 0; tg < G; ++tg) {
        const float4 v = *reinterpret_cast<const float4*>(sr + 8 + 4 * tg);
        w[8] = v.x; w[9] = v.y; w[10] = v.z; w[11] = v.w;
#pragma unroll
        for (int j = 0; j < 4; ++j) {
            const int t = 4 * tg + j;
            S += w[j];
#pragma unroll
            for (int o = 0; o < 8; ++o) {
                aF[o] = fmaf(T.f[t], w[j + o], aF[o]);
                aH[o] = fmaf(T.h[t], w[j + o], aH[o]);
            }
        }
#pragma unroll
        for (int i = 0; i < 8; ++i) w[i] = w[i + 4];
    }
    if (REM == 3) { w[8] = sr[4 * G + 8]; w[9] = sr[4 * G + 9]; }
#pragma unroll
    for (int j = 0; j < REM; ++j) {
        const int t = 4 * G + j;
        S += w[j];
#pragma unroll
        for (int o = 0; o < 8; ++o) {
            aF[o] = fmaf(T.f[t], w[j + o], aF[o]);
            aH[o] = fmaf(T.h[t], w[j + o], aH[o]);
        }
    }

    // sliding box
    float box[8];
    box[0] = S;
#pragma unroll
    for (int o = 1; o < 8; ++o)
        box[o] = box[o - 1] - sr[o - 1] + sr[o + K - 1];

    const int base = (row0 + sub) * Ww + x0;
    float4* __restrict__ fh = g_FH[SI] + base / 2;
#pragma unroll
    for (int o = 0; o < 8; o += 2)
        fh[o / 2] = make_float4(aF[o], aH[o], aF[o + 1], aH[o + 1]);
    float4* __restrict__ a1 = g_A14[SI] + base / 4;
    a1[0] = make_float4(box[0], box[1], box[2], box[3]);
    a1[1] = make_float4(box[4], box[5], box[6], box[7]);
}

__global__ void __launch_bounds__(128) row_all_k() {
    __shared__ alignas(16) float s[2 * PWMAX];
    const int tid  = threadIdx.x;
    const int row0 = blockIdx.x * 2;
    switch (blockIdx.z) {
        case 0: row_body<0>(s, tid, row0); break;
        case 1: row_body<1>(s, tid, row0); break;
        case 2: row_body<2>(s, tid, row0); break;
        case 3: row_body<3>(s, tid, row0); break;
        case 4: row_body<4>(s, tid, row0); break;
        default: row_body<5>(s, tid, row0); break;
    }
}

// ---------------- col pass (all sigmas in one kernel) -----------------------
// R outputs per thread along y; register ring + PF-deep load prefetch.

template<int SI, bool FAST>
__device__ __forceinline__ float col_body(int pb, int y0) {
    constexpr int K = Cfg<SI>::K;
    constexpr TapsT<K> T = make_taps<K>(Cfg<SI>::S);
    constexpr int P = K / 2;
    constexpr int R = Cfg<SI>::CR;
    constexpr int PF = 6;
    constexpr int PI = (PF < K) ? PF : K;

    const float2* __restrict__ FH = (const float2*)g_FH[SI];
    const float*  __restrict__ A1 = (const float*)g_A14[SI];
    const int yb = y0 - P;

    auto ridx = [&](int j) -> int {
        return pb + (FAST ? (yb + j) : refl(yb + j, Hh)) * Ww;
    };

    float af[R], ah[R], acc[R];
#pragma unroll
    for (int o = 0; o < R; ++o) acc[o] = 0.f;

#pragma unroll
    for (int j = 0; j < R - 1; ++j) {
        const float2 v = FH[ridx(j)];
        af[j] = v.x; ah[j] = v.y;
    }
    float2 pend[PF];
#pragma unroll
    for (int q = 0; q < PI; ++q) pend[q] = FH[ridx(R - 1 + q)];

#pragma unroll
    for (int t = 0; t < K; ++t) {
        const float2 v = pend[t % PF];
        if (t + PF < K) pend[t % PF] = FH[ridx(R - 1 + t + PF)];
        const int sl = (t + R - 1) & (R - 1);
        af[sl] = v.x; ah[sl] = v.y;
#pragma unroll
        for (int o = 0; o < R; ++o) {
            const int u = (t + o) & (R - 1);
            acc[o] = fmaf(T.f[t], ah[u], acc[o]);
            acc[o] = fmaf(T.h[t], af[u], acc[o]);
        }
    }

    // box: base window + sliding edges
    float S = 0.f;
#pragma unroll
    for (int j = 0; j < K; ++j) S += A1[ridx(j)];
    float lo[R], hi[R];
#pragma unroll
    for (int o = 1; o < R; ++o) {
        lo[o] = A1[ridx(o - 1)];
        hi[o] = A1[ridx(K - 1 + o)];
    }
    float box = S, local = 0.f;
#pragma unroll
    for (int o = 0; o < R; ++o) {
        if (o) box += hi[o] - lo[o];
        const float v = fmaf(-T.c, box, acc[o]);
        local = fmaf(v, v, local);
    }
    return local;
}

template<int SI>
__device__ __forceinline__ void col_sigma(int img) {
    constexpr int K = Cfg<SI>::K;
    constexpr int P = K / 2;
    constexpr int R = Cfg<SI>::CR;

    if (blockIdx.y >= (unsigned)(Hh / R)) return;   // unused y-blocks for R=32

    const int x  = blockIdx.x * 128 + threadIdx.x;
    const int y0 = blockIdx.y * R;
    const int pb = img * (Hh * Ww) + x;

    const int yb = y0 - P;
    const bool interior = (yb >= 0) && (yb + K + R - 2 < Hh);
    float local = interior ? col_body<SI, true>(pb, y0)
                           : col_body<SI, false>(pb, y0);

#pragma unroll
    for (int off = 16; off; off >>= 1)
        local += __shfl_xor_sync(0xffffffffu, local, off);
    __shared__ float ws[4];
    if ((threadIdx.x & 31) == 0) ws[threadIdx.x >> 5] = local;
    __syncthreads();
    if (threadIdx.x == 0) {
        const double tot = (double)ws[0] + (double)ws[1] + (double)ws[2] + (double)ws[3];
        atomicAdd(&g_acc[SI], tot);
    }
}

__global__ void __launch_bounds__(128) col_all_k() {
    const int si  = blockIdx.z % 6;
    const int img = blockIdx.z / 6;
    switch (si) {
        case 0: col_sigma<0>(img); break;
        case 1: col_sigma<1>(img); break;
        case 2: col_sigma<2>(img); break;
        case 3: col_sigma<3>(img); break;
        case 4: col_sigma<4>(img); break;
        default: col_sigma<5>(img); break;
    }
}

// ---------------- final -----------------------------------------------------

__global__ void final_k(float* __restrict__ out) {
    const double w[6] = {600.0, 500.0, 400.0, 20.0, 10.0, 10.0};
    double l = 0.0;
    for (int i = 0; i < 6; ++i) l += w[i] * g_acc[i];
    out[0] = (float)(l / (double)NPIX);
}

// ---------------- launcher ---------------------------------------------------

extern "C" void kernel_launch(void* const* d_in, const int* in_sizes, int n_in,
                              void* d_out, int out_size) {
    (void)in_sizes; (void)n_in; (void)out_size;
    const float4* a = (const float4*)d_in[0];
    const float4* b = (const float4*)d_in[1];

    diff_k<<<(NPIX / 4 + 511) / 512, 512>>>(a, b);
    row_all_k<<<dim3(NCc * Hh / 2, 1, 6), 128>>>();
    col_all_k<<<dim3(Ww / 128, Hh / 16, NCc * 6), 128>>>();
    final_k<<<1, 1>>>((float*)d_out);
}

// round 5
// speedup vs baseline: 1.4677x; 1.4677x over previous
#include <cuda_runtime.h>

// ---------------------------------------------------------------------------
// SpatialFrequencyLoss: sum_i w_i * mean( (LoG_i * (input - target))^2 )
// LoG kernel is rank-3 separable:  a = f (x) u  +  u (x) f  -  c * ones
// Row pass (along W): FH = packed (aH, aF) per pixel, A1 = diff * box
// Col pass (along H): d = f*aH + h*aF - c*Box ; accumulate d^2
// Packed f32x2 FMA (FFMA2) carries both filters per instruction.
// Shared planes (L2-resident, ~50MB), sequential per-sigma chains.
// Reflect padding (numpy 'reflect'), pad = K/2 < 512 always.
// ---------------------------------------------------------------------------

namespace {
constexpr int Hh = 512, Ww = 512, NCc = 4 * 3;
constexpr int NPIX = NCc * Hh * Ww;  // 3,145,728
}

__device__ float  g_diff[NPIX];
__device__ float4 g_FH[NPIX / 2];    // (aH,aF) pairs, two pixels per float4
__device__ float4 g_A14[NPIX / 4];   // A1 plane
__device__ double g_acc[6];

// ---------------- f32x2 packed helpers --------------------------------------

__device__ __forceinline__ unsigned long long pk2(float lo, float hi) {
    unsigned long long r;
    asm("mov.b64 %0, {%1, %2};" : "=l"(r) : "f"(lo), "f"(hi));
    return r;
}
__device__ __forceinline__ unsigned long long ffma2(unsigned long long a,
                                                    unsigned long long b,
                                                    unsigned long long c) {
    unsigned long long d;
    asm("fma.rn.f32x2 %0, %1, %2, %3;" : "=l"(d) : "l"(a), "l"(b), "l"(c));
    return d;
}
__device__ __forceinline__ float2 upk(unsigned long long a) {
    float2 v;
    asm("mov.b64 {%0, %1}, %2;" : "=f"(v.x), "=f"(v.y) : "l"(a));
    return v;
}

// ---------------- compile-time taps ----------------------------------------

__host__ __device__ constexpr double cexp(double x) {
    double r = x; int n = 0;
    while (r < -0.5) { r += 1.0; ++n; }
    double term = 1.0, sum = 1.0;
    for (int i = 1; i < 30; ++i) { term *= r / (double)i; sum += term; }
    for (int i = 0; i < n; ++i) sum /= 2.71828182845904523536028747135266;
    return sum;
}

template<int K> struct TapsT { float f[K]; float h[K]; float c; };

template<int K>
__host__ __device__ constexpr TapsT<K> make_taps(double sigma) {
    TapsT<K> T{};
    const double ss = sigma * sigma;
    const double norm = 1.0 / (2.0 * 3.14159265358979323846 * ss * ss);
    double Sf = 0.0, Sh = 0.0;
    for (int i = 0; i < K; ++i) {
        const double x = (double)(i - (K - 1) / 2);
        const double u = cexp(-(x * x) / (2.0 * ss));
        const double fv = (x * x - ss) * u * norm;
        T.f[i] = (float)fv;
        T.h[i] = (float)u;
        Sf += fv; Sh += u;
    }
    T.c = (float)(2.0 * Sf * Sh / ((double)K * (double)K));
    return T;
}

template<int SI> struct Cfg;
template<> struct Cfg<0> { static constexpr int K = 5;   static constexpr double S = 0.6;  static constexpr int CR = 16; };
template<> struct Cfg<1> { static constexpr int K = 11;  static constexpr double S = 1.2;  static constexpr int CR = 16; };
template<> struct Cfg<2> { static constexpr int K = 21;  static constexpr double S = 2.4;  static constexpr int CR = 16; };
template<> struct Cfg<3> { static constexpr int K = 39;  static constexpr double S = 4.8;  static constexpr int CR = 16; };
template<> struct Cfg<4> { static constexpr int K = 77;  static constexpr double S = 9.6;  static constexpr int CR = 32; };
template<> struct Cfg<5> { static constexpr int K = 155; static constexpr double S = 19.2; static constexpr int CR = 32; };

__device__ __forceinline__ int refl(int i, int n) {
    if (i < 0) i = -i;
    if (i >= n) i = 2 * n - 2 - i;
    return i;
}

// ---------------- diff ------------------------------------------------------

__global__ void diff_k(const float4* __restrict__ a, const float4* __restrict__ b) {
    if (blockIdx.x == 0 && threadIdx.x < 6) g_acc[threadIdx.x] = 0.0;
    int i = blockIdx.x * blockDim.x + threadIdx.x;
    if (i < NPIX / 4) {
        float4 x = a[i], y = b[i];
        float4 d;
        d.x = x.x - y.x; d.y = x.y - y.y; d.z = x.z - y.z; d.w = x.w - y.w;
        reinterpret_cast<float4*>(g_diff)[i] = d;
    }
}

// ---------------- row pass ---------------------------------------------------
// 128 threads = 2 rows x 64 threads; 8 consecutive outputs/thread.
// Window fed 4 taps at a time from one LDS.128; FFMA2 carries both filters.

template<int SI>
__global__ void __launch_bounds__(128) row_k() {
    constexpr int K = Cfg<SI>::K;
    constexpr TapsT<K> T = make_taps<K>(Cfg<SI>::S);
    constexpr int P = K / 2;
    constexpr int PW = Ww + 2 * P;
    constexpr int PWpad = (PW + 3) & ~3;

    __shared__ alignas(16) float s[2 * PWpad];
    const int tid  = threadIdx.x;
    const int row0 = blockIdx.x * 2;
#pragma unroll
    for (int rr = 0; rr < 2; ++rr) {
        const float* __restrict__ src = g_diff + (row0 + rr) * Ww;
        for (int i = tid; i < PW; i += 128) s[rr * PWpad + i] = src[refl(i - P, Ww)];
    }
    __syncthreads();

    const int sub = tid >> 6;
    const int x0  = (tid & 63) * 8;
    const float* __restrict__ sr = s + sub * PWpad + x0;   // 16B aligned

    float w[12];
#pragma unroll
    for (int i = 0; i < 8; i += 4) {
        const float4 v = *reinterpret_cast<const float4*>(sr + i);
        w[i] = v.x; w[i + 1] = v.y; w[i + 2] = v.z; w[i + 3] = v.w;
    }

    unsigned long long aFH[8];
#pragma unroll
    for (int o = 0; o < 8; ++o) aFH[o] = 0ull;
    float S = 0.f;

    constexpr int G = K / 4, REM = K % 4;
#pragma unroll
    for (int tg = 0; tg < G; ++tg) {
        const float4 v = *reinterpret_cast<const float4*>(sr + 8 + 4 * tg);
        w[8] = v.x; w[9] = v.y; w[10] = v.z; w[11] = v.w;
#pragma unroll
        for (int j = 0; j < 4; ++j) {
            const int t = 4 * tg + j;
            const unsigned long long tp = pk2(T.f[t], T.h[t]);
            const unsigned long long dv = pk2(w[j], w[j]);
            S += w[j];
#pragma unroll
            for (int o = 0; o < 8; ++o) {
                const unsigned long long dd = pk2(w[j + o], w[j + o]);
                aFH[o] = ffma2(tp, dd, aFH[o]);
            }
            (void)dv;
        }
#pragma unroll
        for (int i = 0; i < 8; ++i) w[i] = w[i + 4];
    }
    if (REM == 3) { w[8] = sr[4 * G + 8]; w[9] = sr[4 * G + 9]; }
#pragma unroll
    for (int j = 0; j < REM; ++j) {
        const int t = 4 * G + j;
        const unsigned long long tp = pk2(T.f[t], T.h[t]);
        S += w[j];
#pragma unroll
        for (int o = 0; o < 8; ++o) {
            const unsigned long long dd = pk2(w[j + o], w[j + o]);
            aFH[o] = ffma2(tp, dd, aFH[o]);
        }
    }

    // sliding box
    float box[8];
    box[0] = S;
#pragma unroll
    for (int o = 1; o < 8; ++o)
        box[o] = box[o - 1] - sr[o - 1] + sr[o + K - 1];

    const int base = (row0 + sub) * Ww + x0;
    float4* __restrict__ fh = g_FH + base / 2;
#pragma unroll
    for (int o = 0; o < 8; o += 2) {
        const float2 p0 = upk(aFH[o]);      // x = aF, y = aH
        const float2 p1 = upk(aFH[o + 1]);
        fh[o / 2] = make_float4(p0.y, p0.x, p1.y, p1.x);   // store (aH, aF)
    }
    float4* __restrict__ a1 = g_A14 + base / 4;
    a1[0] = make_float4(box[0], box[1], box[2], box[3]);
    a1[1] = make_float4(box[4], box[5], box[6], box[7]);
}

// ---------------- col pass ---------------------------------------------------
// R outputs/thread along y; packed u64 ring + PF-deep prefetch; FFMA2 inner.

template<int SI, bool FAST>
__device__ __forceinline__ float col_body(int pb, int y0) {
    constexpr int K = Cfg<SI>::K;
    constexpr TapsT<K> T = make_taps<K>(Cfg<SI>::S);
    constexpr int P = K / 2;
    constexpr int R = Cfg<SI>::CR;
    constexpr int PF = 6;
    constexpr int PI = (PF < K) ? PF : K;

    const unsigned long long* __restrict__ FH = (const unsigned long long*)g_FH;
    const float* __restrict__ A1 = (const float*)g_A14;
    const int yb = y0 - P;

    auto ridx = [&](int j) -> int {
        return pb + (FAST ? (yb + j) : refl(yb + j, Hh)) * Ww;
    };

    unsigned long long ring[R], acc[R];
#pragma unroll
    for (int o = 0; o < R; ++o) acc[o] = 0ull;

#pragma unroll
    for (int j = 0; j < R - 1; ++j) ring[j] = FH[ridx(j)];
    unsigned long long pend[PF];
#pragma unroll
    for (int q = 0; q < PI; ++q) pend[q] = FH[ridx(R - 1 + q)];

#pragma unroll
    for (int t = 0; t < K; ++t) {
        const unsigned long long v = pend[t % PF];
        if (t + PF < K) pend[t % PF] = FH[ridx(R - 1 + t + PF)];
        const int sl = (t + R - 1) & (R - 1);
        ring[sl] = v;
        const unsigned long long tp = pk2(T.f[t], T.h[t]);
#pragma unroll
        for (int o = 0; o < R; ++o)
            acc[o] = ffma2(tp, ring[(t + o) & (R - 1)], acc[o]);
    }

    // box: base window sum, then slide with inline (L1-hot) edge loads
    float S = 0.f;
#pragma unroll
    for (int j = 0; j < K; ++j) S += A1[ridx(j)];

    float box = S, local = 0.f;
#pragma unroll
    for (int o = 0; o < R; ++o) {
        if (o) box += A1[ridx(K - 1 + o)] - A1[ridx(o - 1)];
        const float2 sfh = upk(acc[o]);
        const float v = fmaf(-T.c, box, sfh.x + sfh.y);
        local = fmaf(v, v, local);
    }
    return local;
}

template<int SI>
__global__ void __launch_bounds__(128) col_k() {
    constexpr int K = Cfg<SI>::K;
    constexpr int P = K / 2;
    constexpr int R = Cfg<SI>::CR;

    const int x  = blockIdx.x * 128 + threadIdx.x;
    const int y0 = blockIdx.y * R;
    const int pb = blockIdx.z * (Hh * Ww) + x;

    const int yb = y0 - P;
    const bool interior = (yb >= 0) && (yb + K + R - 2 < Hh);
    float local = interior ? col_body<SI, true>(pb, y0)
                           : col_body<SI, false>(pb, y0);

#pragma unroll
    for (int off = 16; off; off >>= 1)
        local += __shfl_xor_sync(0xffffffffu, local, off);
    __shared__ float ws[4];
    if ((threadIdx.x & 31) == 0) ws[threadIdx.x >> 5] = local;
    __syncthreads();
    if (threadIdx.x == 0) {
        const double tot = (double)ws[0] + (double)ws[1] + (double)ws[2] + (double)ws[3];
        atomicAdd(&g_acc[SI], tot);
    }
}

// ---------------- final -----------------------------------------------------

__global__ void final_k(float* __restrict__ out) {
    const double w[6] = {600.0, 500.0, 400.0, 20.0, 10.0, 10.0};
    double l = 0.0;
    for (int i = 0; i < 6; ++i) l += w[i] * g_acc[i];
    out[0] = (float)(l / (double)NPIX);
}

// ---------------- launcher ---------------------------------------------------

template<int SI> static void run_sigma() {
    row_k<SI><<<NCc * Hh / 2, 128>>>();
    col_k<SI><<<dim3(Ww / 128, Hh / Cfg<SI>::CR, NCc), 128>>>();
}

extern "C" void kernel_launch(void* const* d_in, const int* in_sizes, int n_in,
                              void* d_out, int out_size) {
    (void)in_sizes; (void)n_in; (void)out_size;
    const float4* a = (const float4*)d_in[0];
    const float4* b = (const float4*)d_in[1];

    diff_k<<<(NPIX / 4 + 511) / 512, 512>>>(a, b);
    run_sigma<0>();
    run_sigma<1>();
    run_sigma<2>();
    run_sigma<3>();
    run_sigma<4>();
    run_sigma<5>();
    final_k<<<1, 1>>>((float*)d_out);
}

// round 6
// speedup vs baseline: 1.6401x; 1.1175x over previous
#include <cuda_runtime.h>

// ---------------------------------------------------------------------------
// SpatialFrequencyLoss: sum_i w_i * mean( (LoG_i * (input - target))^2 )
// LoG kernel is rank-3 separable:  a = f (x) u  +  u (x) f  -  c * ones
// Row pass (along W): FH = packed (aH, aF) per pixel, A1 = diff * box
// Col pass (along H): d = f*aH + h*aF - c*Box ; accumulate d^2
// Six independent sigma chains run on 3 concurrent streams (graph fork/join),
// each pair of chains owning a private plane set (all 3 sets L2-resident).
// Reflect padding (numpy 'reflect'), pad = K/2 < 512 always.
// ---------------------------------------------------------------------------

namespace {
constexpr int Hh = 512, Ww = 512, NCc = 4 * 3;
constexpr int NPIX = NCc * Hh * Ww;  // 3,145,728
}

__device__ float  g_diff[NPIX];
__device__ float4 g_FH3[3][NPIX / 2];    // per-stream (aH,aF) pairs
__device__ float4 g_A143[3][NPIX / 4];   // per-stream A1 plane
__device__ double g_acc[6];

// ---------------- f32x2 packed helpers --------------------------------------

__device__ __forceinline__ unsigned long long pk2(float lo, float hi) {
    unsigned long long r;
    asm("mov.b64 %0, {%1, %2};" : "=l"(r) : "f"(lo), "f"(hi));
    return r;
}
__device__ __forceinline__ unsigned long long ffma2(unsigned long long a,
                                                    unsigned long long b,
                                                    unsigned long long c) {
    unsigned long long d;
    asm("fma.rn.f32x2 %0, %1, %2, %3;" : "=l"(d) : "l"(a), "l"(b), "l"(c));
    return d;
}
__device__ __forceinline__ float2 upk(unsigned long long a) {
    float2 v;
    asm("mov.b64 {%0, %1}, %2;" : "=f"(v.x), "=f"(v.y) : "l"(a));
    return v;
}

// ---------------- compile-time taps ----------------------------------------

__host__ __device__ constexpr double cexp(double x) {
    double r = x; int n = 0;
    while (r < -0.5) { r += 1.0; ++n; }
    double term = 1.0, sum = 1.0;
    for (int i = 1; i < 30; ++i) { term *= r / (double)i; sum += term; }
    for (int i = 0; i < n; ++i) sum /= 2.71828182845904523536028747135266;
    return sum;
}

template<int K> struct TapsT { float f[K]; float h[K]; float c; };

template<int K>
__host__ __device__ constexpr TapsT<K> make_taps(double sigma) {
    TapsT<K> T{};
    const double ss = sigma * sigma;
    const double norm = 1.0 / (2.0 * 3.14159265358979323846 * ss * ss);
    double Sf = 0.0, Sh = 0.0;
    for (int i = 0; i < K; ++i) {
        const double x = (double)(i - (K - 1) / 2);
        const double u = cexp(-(x * x) / (2.0 * ss));
        const double fv = (x * x - ss) * u * norm;
        T.f[i] = (float)fv;
        T.h[i] = (float)u;
        Sf += fv; Sh += u;
    }
    T.c = (float)(2.0 * Sf * Sh / ((double)K * (double)K));
    return T;
}

template<int SI> struct Cfg;
template<> struct Cfg<0> { static constexpr int K = 5;   static constexpr double S = 0.6;  static constexpr int CR = 16; };
template<> struct Cfg<1> { static constexpr int K = 11;  static constexpr double S = 1.2;  static constexpr int CR = 16; };
template<> struct Cfg<2> { static constexpr int K = 21;  static constexpr double S = 2.4;  static constexpr int CR = 16; };
template<> struct Cfg<3> { static constexpr int K = 39;  static constexpr double S = 4.8;  static constexpr int CR = 16; };
template<> struct Cfg<4> { static constexpr int K = 77;  static constexpr double S = 9.6;  static constexpr int CR = 32; };
template<> struct Cfg<5> { static constexpr int K = 155; static constexpr double S = 19.2; static constexpr int CR = 32; };

__device__ __forceinline__ int refl(int i, int n) {
    if (i < 0) i = -i;
    if (i >= n) i = 2 * n - 2 - i;
    return i;
}

// ---------------- diff ------------------------------------------------------

__global__ void diff_k(const float4* __restrict__ a, const float4* __restrict__ b) {
    if (blockIdx.x == 0 && threadIdx.x < 6) g_acc[threadIdx.x] = 0.0;
    int i = blockIdx.x * blockDim.x + threadIdx.x;
    if (i < NPIX / 4) {
        float4 x = a[i], y = b[i];
        float4 d;
        d.x = x.x - y.x; d.y = x.y - y.y; d.z = x.z - y.z; d.w = x.w - y.w;
        reinterpret_cast<float4*>(g_diff)[i] = d;
    }
}

// ---------------- row pass ---------------------------------------------------
// 128 threads = 2 rows x 64 threads; 8 consecutive outputs/thread.
// Window fed 4 taps at a time from one LDS.128; FFMA2 carries both filters.

template<int SI>
__global__ void __launch_bounds__(128) row_k(int ps) {
    constexpr int K = Cfg<SI>::K;
    constexpr TapsT<K> T = make_taps<K>(Cfg<SI>::S);
    constexpr int P = K / 2;
    constexpr int PW = Ww + 2 * P;
    constexpr int PWpad = (PW + 3) & ~3;

    __shared__ alignas(16) float s[2 * PWpad];
    const int tid  = threadIdx.x;
    const int row0 = blockIdx.x * 2;
#pragma unroll
    for (int rr = 0; rr < 2; ++rr) {
        const float* __restrict__ src = g_diff + (row0 + rr) * Ww;
        for (int i = tid; i < PW; i += 128) s[rr * PWpad + i] = src[refl(i - P, Ww)];
    }
    __syncthreads();

    const int sub = tid >> 6;
    const int x0  = (tid & 63) * 8;
    const float* __restrict__ sr = s + sub * PWpad + x0;   // 16B aligned

    float w[12];
#pragma unroll
    for (int i = 0; i < 8; i += 4) {
        const float4 v = *reinterpret_cast<const float4*>(sr + i);
        w[i] = v.x; w[i + 1] = v.y; w[i + 2] = v.z; w[i + 3] = v.w;
    }

    unsigned long long aFH[8];
#pragma unroll
    for (int o = 0; o < 8; ++o) aFH[o] = 0ull;
    float S = 0.f;

    constexpr int G = K / 4, REM = K % 4;
#pragma unroll
    for (int tg = 0; tg < G; ++tg) {
        const float4 v = *reinterpret_cast<const float4*>(sr + 8 + 4 * tg);
        w[8] = v.x; w[9] = v.y; w[10] = v.z; w[11] = v.w;
#pragma unroll
        for (int j = 0; j < 4; ++j) {
            const int t = 4 * tg + j;
            const unsigned long long tp = pk2(T.f[t], T.h[t]);
            S += w[j];
#pragma unroll
            for (int o = 0; o < 8; ++o) {
                const unsigned long long dd = pk2(w[j + o], w[j + o]);
                aFH[o] = ffma2(tp, dd, aFH[o]);
            }
        }
#pragma unroll
        for (int i = 0; i < 8; ++i) w[i] = w[i + 4];
    }
    if (REM == 3) { w[8] = sr[4 * G + 8]; w[9] = sr[4 * G + 9]; }
#pragma unroll
    for (int j = 0; j < REM; ++j) {
        const int t = 4 * G + j;
        const unsigned long long tp = pk2(T.f[t], T.h[t]);
        S += w[j];
#pragma unroll
        for (int o = 0; o < 8; ++o) {
            const unsigned long long dd = pk2(w[j + o], w[j + o]);
            aFH[o] = ffma2(tp, dd, aFH[o]);
        }
    }

    // sliding box
    float box[8];
    box[0] = S;
#pragma unroll
    for (int o = 1; o < 8; ++o)
        box[o] = box[o - 1] - sr[o - 1] + sr[o + K - 1];

    const int base = (row0 + sub) * Ww + x0;
    float4* __restrict__ fh = g_FH3[ps] + base / 2;
#pragma unroll
    for (int o = 0; o < 8; o += 2) {
        const float2 p0 = upk(aFH[o]);      // x = aF, y = aH
        const float2 p1 = upk(aFH[o + 1]);
        fh[o / 2] = make_float4(p0.y, p0.x, p1.y, p1.x);   // store (aH, aF)
    }
    float4* __restrict__ a1 = g_A143[ps] + base / 4;
    a1[0] = make_float4(box[0], box[1], box[2], box[3]);
    a1[1] = make_float4(box[4], box[5], box[6], box[7]);
}

// ---------------- col pass ---------------------------------------------------
// R outputs/thread along y; packed u64 ring + PF-deep prefetch; FFMA2 inner.

template<int SI, bool FAST>
__device__ __forceinline__ float col_body(int ps, int pb, int y0) {
    constexpr int K = Cfg<SI>::K;
    constexpr TapsT<K> T = make_taps<K>(Cfg<SI>::S);
    constexpr int P = K / 2;
    constexpr int R = Cfg<SI>::CR;
    constexpr int PF = 6;
    constexpr int PI = (PF < K) ? PF : K;

    const unsigned long long* __restrict__ FH = (const unsigned long long*)g_FH3[ps];
    const float* __restrict__ A1 = (const float*)g_A143[ps];
    const int yb = y0 - P;

    auto ridx = [&](int j) -> int {
        return pb + (FAST ? (yb + j) : refl(yb + j, Hh)) * Ww;
    };

    unsigned long long ring[R], acc[R];
#pragma unroll
    for (int o = 0; o < R; ++o) acc[o] = 0ull;

#pragma unroll
    for (int j = 0; j < R - 1; ++j) ring[j] = FH[ridx(j)];
    unsigned long long pend[PF];
#pragma unroll
    for (int q = 0; q < PI; ++q) pend[q] = FH[ridx(R - 1 + q)];

#pragma unroll
    for (int t = 0; t < K; ++t) {
        const unsigned long long v = pend[t % PF];
        if (t + PF < K) pend[t % PF] = FH[ridx(R - 1 + t + PF)];
        const int sl = (t + R - 1) & (R - 1);
        ring[sl] = v;
        const unsigned long long tp = pk2(T.f[t], T.h[t]);
#pragma unroll
        for (int o = 0; o < R; ++o)
            acc[o] = ffma2(tp, ring[(t + o) & (R - 1)], acc[o]);
    }

    // box: base window sum, then slide with inline (L1-hot) edge loads
    float S = 0.f;
#pragma unroll
    for (int j = 0; j < K; ++j) S += A1[ridx(j)];

    float box = S, local = 0.f;
#pragma unroll
    for (int o = 0; o < R; ++o) {
        if (o) box += A1[ridx(K - 1 + o)] - A1[ridx(o - 1)];
        const float2 sfh = upk(acc[o]);
        const float v = fmaf(-T.c, box, sfh.x + sfh.y);
        local = fmaf(v, v, local);
    }
    return local;
}

template<int SI>
__global__ void __launch_bounds__(128) col_k(int ps) {
    constexpr int K = Cfg<SI>::K;
    constexpr int P = K / 2;
    constexpr int R = Cfg<SI>::CR;

    const int x  = blockIdx.x * 128 + threadIdx.x;
    const int y0 = blockIdx.y * R;
    const int pb = blockIdx.z * (Hh * Ww) + x;

    const int yb = y0 - P;
    const bool interior = (yb >= 0) && (yb + K + R - 2 < Hh);
    float local = interior ? col_body<SI, true>(ps, pb, y0)
                           : col_body<SI, false>(ps, pb, y0);

#pragma unroll
    for (int off = 16; off; off >>= 1)
        local += __shfl_xor_sync(0xffffffffu, local, off);
    __shared__ float ws[4];
    if ((threadIdx.x & 31) == 0) ws[threadIdx.x >> 5] = local;
    __syncthreads();
    if (threadIdx.x == 0) {
        const double tot = (double)ws[0] + (double)ws[1] + (double)ws[2] + (double)ws[3];
        atomicAdd(&g_acc[SI], tot);
    }
}

// ---------------- final -----------------------------------------------------

__global__ void final_k(float* __restrict__ out) {
    const double w[6] = {600.0, 500.0, 400.0, 20.0, 10.0, 10.0};
    double l = 0.0;
    for (int i = 0; i < 6; ++i) l += w[i] * g_acc[i];
    out[0] = (float)(l / (double)NPIX);
}

// ---------------- launcher ---------------------------------------------------

template<int SI> static void run_sigma(cudaStream_t st, int ps) {
    row_k<SI><<<NCc * Hh / 2, 128, 0, st>>>(ps);
    col_k<SI><<<dim3(Ww / 128, Hh / Cfg<SI>::CR, NCc), 128, 0, st>>>(ps);
}

extern "C" void kernel_launch(void* const* d_in, const int* in_sizes, int n_in,
                              void* d_out, int out_size) {
    (void)in_sizes; (void)n_in; (void)out_size;
    const float4* a = (const float4*)d_in[0];
    const float4* b = (const float4*)d_in[1];

    // one-time host resources (created on the uncaptured correctness call)
    static cudaStream_t sA = nullptr, sB = nullptr, sC = nullptr;
    static cudaEvent_t eD = nullptr, eA = nullptr, eB = nullptr, eC = nullptr;
    if (!sA) {
        cudaStreamCreateWithFlags(&sA, cudaStreamNonBlocking);
        cudaStreamCreateWithFlags(&sB, cudaStreamNonBlocking);
        cudaStreamCreateWithFlags(&sC, cudaStreamNonBlocking);
        cudaEventCreateWithFlags(&eD, cudaEventDisableTiming);
        cudaEventCreateWithFlags(&eA, cudaEventDisableTiming);
        cudaEventCreateWithFlags(&eB, cudaEventDisableTiming);
        cudaEventCreateWithFlags(&eC, cudaEventDisableTiming);
    }

    diff_k<<<(NPIX / 4 + 511) / 512, 512>>>(a, b);   // legacy stream
    cudaEventRecord(eD, 0);
    cudaStreamWaitEvent(sA, eD, 0);
    cudaStreamWaitEvent(sB, eD, 0);
    cudaStreamWaitEvent(sC, eD, 0);

    // chain A: sigma5 + sigma0 (plane set 0)
    run_sigma<5>(sA, 0);
    run_sigma<0>(sA, 0);
    // chain B: sigma4 + sigma2 (plane set 1)
    run_sigma<4>(sB, 1);
    run_sigma<2>(sB, 1);
    // chain C: sigma3 + sigma1 (plane set 2)
    run_sigma<3>(sC, 2);
    run_sigma<1>(sC, 2);

    cudaEventRecord(eA, sA);
    cudaEventRecord(eB, sB);
    cudaEventRecord(eC, sC);
    cudaStreamWaitEvent(0, eA, 0);
    cudaStreamWaitEvent(0, eB, 0);
    cudaStreamWaitEvent(0, eC, 0);

    final_k<<<1, 1>>>((float*)d_out);                // legacy stream
}